// round 7
// baseline (speedup 1.0000x reference)
#include <cuda_runtime.h>
#include <math.h>

#define NN 100000
#define NG 64
#define D  128
#define EMAX 2000000

// -------- scratch (device globals; no runtime allocation) --------
__device__ float g_h   [(size_t)NN * D];  // GEMM output
__device__ float g_agg [(size_t)NN * D];  // layer-2 aggregated output (pool input)
__device__ float g_elu [(size_t)NN * D];  // elu(layer-1 agg) = layer-2 GEMM input
__device__ float g_dinv[NN];              // deg^{-1/2}
__device__ int   g_cnti[NN];              // edge counts per dst
__device__ int   g_off [NN + 1];          // CSR offsets
__device__ int   g_cur [NN];              // fill cursors
__device__ int   g_srcs[EMAX];            // CSR adjacency (src per edge, grouped by dst)
__device__ float g_pool[NG * D];
__device__ float g_cnt [NG];

// ---------------- CSR build ----------------
__global__ void k_zero_cnt() {
    int i = blockIdx.x * blockDim.x + threadIdx.x;
    if (i < NN) g_cnti[i] = 0;
}

__global__ void k_count(const int* __restrict__ ei, int E) {
    int e = blockIdx.x * blockDim.x + threadIdx.x;
    if (e >= E) return;
    unsigned dst = (unsigned)ei[(size_t)E + e];
    if (dst < NN) atomicAdd(&g_cnti[dst], 1);
}

#define SCAN_T 1024
__global__ void k_scan() {   // single block: scan g_cnti -> g_off/g_cur, also dinv
    __shared__ int ssum[SCAN_T];
    int t = threadIdx.x;
    int per = (NN + SCAN_T - 1) / SCAN_T;
    int lo = t * per, hi = lo + per; if (hi > NN) hi = NN;
    int s = 0;
    for (int i = lo; i < hi; i++) s += g_cnti[i];
    ssum[t] = s;
    __syncthreads();
    for (int ofs = 1; ofs < SCAN_T; ofs <<= 1) {
        int v = (t >= ofs) ? ssum[t - ofs] : 0;
        __syncthreads();
        ssum[t] += v;
        __syncthreads();
    }
    int run = (t == 0) ? 0 : ssum[t - 1];
    for (int i = lo; i < hi; i++) {
        int c = g_cnti[i];
        g_off[i] = run; g_cur[i] = run;
        g_dinv[i] = rsqrtf((float)c + 1.0f);   // +1 self loop
        run += c;
    }
    if (t == SCAN_T - 1) g_off[NN] = run;
}

__global__ void k_fill(const int* __restrict__ ei, int E) {
    int e = blockIdx.x * blockDim.x + threadIdx.x;
    if (e >= E) return;
    unsigned src = (unsigned)ei[e];
    unsigned dst = (unsigned)ei[(size_t)E + e];
    if (src >= NN || dst >= NN) return;
    int pos = atomicAdd(&g_cur[dst], 1);
    if (pos < EMAX) g_srcs[pos] = (int)src;
}

// ---------------- SGEMM: g_h = X @ W   (128x128x32 tiles, 8x8 microtile) --
#define BM 128
#define BN 128
#define BKK 32
#define KTILES (D / BKK)   // 4

__device__ __forceinline__
void gemm_body(const float* __restrict__ X, const float* __restrict__ W) {
    __shared__ float sA[BKK][BM];   // 16 KB, [k][m] (transposed)
    __shared__ float sB[BKK][BN];   // 16 KB, [k][n]

    int tid = threadIdx.x;
    int tm  = tid >> 4;            // 0..15
    int tn  = tid & 15;            // 0..15
    int m0  = blockIdx.x * BM;

    // A-load mapping: thread covers half a row (16 floats = 4 float4)
    int arow = tid >> 1;           // 0..127
    int ak0  = (tid & 1) * 16;     // k-local base: 0 or 16

    float acc[8][8];
#pragma unroll
    for (int i = 0; i < 8; i++)
#pragma unroll
        for (int j = 0; j < 8; j++) acc[i][j] = 0.f;

    float4 ra[4], rb[4];

    // prologue: load tile 0 into regs
    {
        int row = m0 + arow;
        const float4* xr = (const float4*)(X + (size_t)row * D) + (ak0 >> 2);
#pragma unroll
        for (int i = 0; i < 4; i++)
            ra[i] = (row < NN) ? __ldg(&xr[i]) : make_float4(0.f, 0.f, 0.f, 0.f);
        const float4* wg = (const float4*)(W);    // tile 0 at W + 0
#pragma unroll
        for (int i = 0; i < 4; i++)
            rb[i] = __ldg(&wg[tid + 256 * i]);
    }

    for (int t = 0; t < KTILES; t++) {
        // store staged regs to smem
#pragma unroll
        for (int i = 0; i < 4; i++) {
            sA[ak0 + i * 4 + 0][arow] = ra[i].x;
            sA[ak0 + i * 4 + 1][arow] = ra[i].y;
            sA[ak0 + i * 4 + 2][arow] = ra[i].z;
            sA[ak0 + i * 4 + 3][arow] = ra[i].w;
        }
#pragma unroll
        for (int i = 0; i < 4; i++)
            ((float4*)&sB[0][0])[tid + 256 * i] = rb[i];
        __syncthreads();

        // prefetch next tile into regs (overlaps compute below)
        if (t + 1 < KTILES) {
            int kt = (t + 1) * BKK;
            int row = m0 + arow;
            const float4* xr = (const float4*)(X + (size_t)row * D + kt) + (ak0 >> 2);
#pragma unroll
            for (int i = 0; i < 4; i++)
                ra[i] = (row < NN) ? __ldg(&xr[i]) : make_float4(0.f, 0.f, 0.f, 0.f);
            const float4* wg = (const float4*)(W + (size_t)kt * D);
#pragma unroll
            for (int i = 0; i < 4; i++)
                rb[i] = __ldg(&wg[tid + 256 * i]);
        }

#pragma unroll
        for (int k = 0; k < BKK; k++) {
            float4 a0 = *(float4*)&sA[k][tm * 4];
            float4 a1 = *(float4*)&sA[k][64 + tm * 4];
            float4 b0 = *(float4*)&sB[k][tn * 4];
            float4 b1 = *(float4*)&sB[k][64 + tn * 4];
            float av[8] = {a0.x, a0.y, a0.z, a0.w, a1.x, a1.y, a1.z, a1.w};
            float bv[8] = {b0.x, b0.y, b0.z, b0.w, b1.x, b1.y, b1.z, b1.w};
#pragma unroll
            for (int i = 0; i < 8; i++)
#pragma unroll
                for (int j = 0; j < 8; j++)
                    acc[i][j] = fmaf(av[i], bv[j], acc[i][j]);
        }
        __syncthreads();
    }

    // epilogue: rows {m0+tm*4+i, m0+64+tm*4+i}, cols {tn*4, 64+tn*4}
#pragma unroll
    for (int half = 0; half < 2; half++) {
#pragma unroll
        for (int i = 0; i < 4; i++) {
            int row = m0 + half * 64 + tm * 4 + i;
            if (row >= NN) continue;
            int ri = half * 4 + i;
            float* hp = g_h + (size_t)row * D;
            *(float4*)(hp + tn * 4)      = make_float4(acc[ri][0], acc[ri][1], acc[ri][2], acc[ri][3]);
            *(float4*)(hp + 64 + tn * 4) = make_float4(acc[ri][4], acc[ri][5], acc[ri][6], acc[ri][7]);
        }
    }
}

__global__ __launch_bounds__(256, 2)
void k_gemm_l1(const float* __restrict__ X, const float* __restrict__ W) {
    gemm_body(X, W);
}

__global__ __launch_bounds__(256, 2)
void k_gemm_l2(const float* __restrict__ W) {
    gemm_body(g_elu, W);
}

// ---------------- CSR gather aggregation (warp per node) -----------------
// out[n] = bias + dinv[n] * ( dinv[n]*h[n] + sum_{s in N(n)} dinv[s]*h[s] )
template<bool DO_ELU>
__global__ void k_gather(const float* __restrict__ bias) {
    int node = (blockIdx.x * blockDim.x + threadIdx.x) >> 5;
    int lane = threadIdx.x & 31;
    if (node >= NN) return;

    float dv = g_dinv[node];
    float4 self = __ldg((const float4*)(g_h + (size_t)node * D) + lane);
    float4 acc = make_float4(self.x * dv, self.y * dv, self.z * dv, self.w * dv);

    int j   = g_off[node];
    int end = g_off[node + 1];
    for (; j + 4 <= end; j += 4) {
        int s0 = __ldg(&g_srcs[j + 0]);
        int s1 = __ldg(&g_srcs[j + 1]);
        int s2 = __ldg(&g_srcs[j + 2]);
        int s3 = __ldg(&g_srcs[j + 3]);
        float d0 = __ldg(&g_dinv[s0]);
        float d1 = __ldg(&g_dinv[s1]);
        float d2 = __ldg(&g_dinv[s2]);
        float d3 = __ldg(&g_dinv[s3]);
        float4 v0 = __ldg((const float4*)(g_h + (size_t)s0 * D) + lane);
        float4 v1 = __ldg((const float4*)(g_h + (size_t)s1 * D) + lane);
        float4 v2 = __ldg((const float4*)(g_h + (size_t)s2 * D) + lane);
        float4 v3 = __ldg((const float4*)(g_h + (size_t)s3 * D) + lane);
        acc.x += v0.x * d0 + v1.x * d1 + v2.x * d2 + v3.x * d3;
        acc.y += v0.y * d0 + v1.y * d1 + v2.y * d2 + v3.y * d3;
        acc.z += v0.z * d0 + v1.z * d1 + v2.z * d2 + v3.z * d3;
        acc.w += v0.w * d0 + v1.w * d1 + v2.w * d2 + v3.w * d3;
    }
    for (; j < end; j++) {
        int s = __ldg(&g_srcs[j]);
        float d = __ldg(&g_dinv[s]);
        float4 v = __ldg((const float4*)(g_h + (size_t)s * D) + lane);
        acc.x += v.x * d; acc.y += v.y * d;
        acc.z += v.z * d; acc.w += v.w * d;
    }

    float4 b = __ldg((const float4*)bias + lane);
    acc.x = b.x + dv * acc.x;
    acc.y = b.y + dv * acc.y;
    acc.z = b.z + dv * acc.z;
    acc.w = b.w + dv * acc.w;

    if (DO_ELU) {
        acc.x = acc.x > 0.f ? acc.x : expm1f(acc.x);
        acc.y = acc.y > 0.f ? acc.y : expm1f(acc.y);
        acc.z = acc.z > 0.f ? acc.z : expm1f(acc.z);
        acc.w = acc.w > 0.f ? acc.w : expm1f(acc.w);
        ((float4*)(g_elu + (size_t)node * D))[lane] = acc;
    } else {
        ((float4*)(g_agg + (size_t)node * D))[lane] = acc;
    }
}

// ---------------- pooling ----------------
__global__ void k_zero_pool() {
    int i = blockIdx.x * blockDim.x + threadIdx.x;
    if (i < NG * D) g_pool[i] = 0.f;
    if (i < NG) g_cnt[i] = 0.f;
}

#define NPB 256
__global__ void k_pool(const int* __restrict__ batch) {
    int f = threadIdx.x;
    int start = blockIdx.x * NPB;
    if (start >= NN) return;
    int end = start + NPB; if (end > NN) end = NN;

    float acc = 0.f;
    int cur = batch[start];
    if ((unsigned)cur >= NG) cur = 0;
    for (int n = start; n < end; n++) {
        int b = batch[n];
        if ((unsigned)b >= NG) b = 0;
        if (b != cur) {
            atomicAdd(&g_pool[cur * D + f], acc);
            acc = 0.f; cur = b;
        }
        acc += g_agg[(size_t)n * D + f];
    }
    atomicAdd(&g_pool[cur * D + f], acc);

    if (f == 0) {
        float c = 0.f;
        int cur2 = batch[start];
        if ((unsigned)cur2 >= NG) cur2 = 0;
        for (int n = start; n < end; n++) {
            int b = batch[n];
            if ((unsigned)b >= NG) b = 0;
            if (b != cur2) { atomicAdd(&g_cnt[cur2], c); c = 0.f; cur2 = b; }
            c += 1.0f;
        }
        atomicAdd(&g_cnt[cur2], c);
    }
}

// ---------------- final MLP + log_softmax ----------------
__global__ void k_mlp(const float* __restrict__ fc1W, const float* __restrict__ fc1b,
                      const float* __restrict__ fc2W, const float* __restrict__ fc2b,
                      float* __restrict__ out) {
    int g = blockIdx.x;
    int lane = threadIdx.x;
    __shared__ float mean[D];
    __shared__ float m1[20];
    __shared__ float z[10];
    __shared__ float lse;

    float cnt = fmaxf(g_cnt[g], 1.0f);
    for (int k = lane; k < D; k += 32) mean[k] = g_pool[g * D + k] / cnt;
    __syncwarp();

    if (lane < 20) {
        float s = fc1b[lane];
        for (int k = 0; k < D; k++) s = fmaf(mean[k], fc1W[k * 20 + lane], s);
        m1[lane] = fmaxf(s, 0.0f);
    }
    __syncwarp();

    if (lane < 10) {
        float s = fc2b[lane];
        for (int k = 0; k < 20; k++) s = fmaf(m1[k], fc2W[k * 10 + lane], s);
        z[lane] = s;
    }
    __syncwarp();

    if (lane == 0) {
        float mx = z[0];
        for (int j = 1; j < 10; j++) mx = fmaxf(mx, z[j]);
        float s = 0.f;
        for (int j = 0; j < 10; j++) s += expf(z[j] - mx);
        lse = mx + logf(s);
    }
    __syncwarp();

    if (lane < 10) out[g * 10 + lane] = z[lane] - lse;
}

// ---------------- launch ----------------
extern "C" void kernel_launch(void* const* d_in, const int* in_sizes, int n_in,
                              void* d_out, int out_size) {
    int ix = -1, iei = -1, ib = -1, iW[2] = {-1, -1}, ibias[2] = {-1, -1};
    int if1W = -1, if1b = -1, if2W = -1, if2b = -1;
    int nW = 0, nbias = 0;
    for (int i = 0; i < n_in; i++) {
        int s = in_sizes[i];
        if      (s == NN * D)            ix = i;
        else if (s == NN)                ib = i;
        else if (s == D * D && nW < 2)   iW[nW++] = i;
        else if (s == D && nbias < 2)    ibias[nbias++] = i;
        else if (s == D * 20)            if1W = i;
        else if (s == 20)                if1b = i;
        else if (s == 20 * 10)           if2W = i;
        else if (s == 10)                if2b = i;
        else if (s > NN)                 iei = i;
    }
    bool ok = (ix >= 0 && iei >= 0 && ib >= 0 && nW == 2 && nbias == 2 &&
               if1W >= 0 && if1b >= 0 && if2W >= 0 && if2b >= 0);
    if (!ok) {
        ix = 0; iei = 1; ib = 2; iW[0] = 3; ibias[0] = 4; iW[1] = 5; ibias[1] = 6;
        if1W = 7; if1b = 8; if2W = 9; if2b = 10;
    }

    const float* x     = (const float*)d_in[ix];
    const int*   ei    = (const int*)d_in[iei];
    const int*   batch = (const int*)d_in[ib];
    const float* W1   = (const float*)d_in[iW[0]];
    const float* b1   = (const float*)d_in[ibias[0]];
    const float* W2   = (const float*)d_in[iW[1]];
    const float* b2   = (const float*)d_in[ibias[1]];
    const float* fc1W = (const float*)d_in[if1W];
    const float* fc1b = (const float*)d_in[if1b];
    const float* fc2W = (const float*)d_in[if2W];
    const float* fc2b = (const float*)d_in[if2b];
    float* out = (float*)d_out;

    int E = in_sizes[iei] / 2;

    const int T = 256;
    int nb_nodes  = (NN + T - 1) / T;
    int nb_edges  = (E + T - 1) / T;
    int nb_gemm   = (NN + BM - 1) / BM;
    int nb_gather = (int)(((size_t)NN * 32 + T - 1) / T);
    int nb_pool   = (NN + NPB - 1) / NPB;

    // CSR build + normalization (once, reused by both layers)
    k_zero_cnt<<<nb_nodes, T>>>();
    k_count<<<nb_edges, T>>>(ei, E);
    k_scan<<<1, SCAN_T>>>();
    k_fill<<<nb_edges, T>>>(ei, E);

    // layer 1
    k_gemm_l1<<<nb_gemm, 256>>>(x, W1);
    k_gather<true><<<nb_gather, T>>>(b1);    // -> g_elu

    // layer 2
    k_gemm_l2<<<nb_gemm, 256>>>(W2);
    k_gather<false><<<nb_gather, T>>>(b2);   // -> g_agg

    // pool + mlp + log_softmax
    k_zero_pool<<<(NG * D + T - 1) / T, T>>>();
    k_pool<<<nb_pool, D>>>(batch);
    k_mlp<<<NG, 32>>>(fc1W, fc1b, fc2W, fc2b, out);
}